// round 12
// baseline (speedup 1.0000x reference)
#include <cuda_runtime.h>
#include <cuda_fp16.h>
#include <math.h>
#include <stdint.h>

// Problem shapes (fixed)
#define Bq 2
#define Nq 2048
#define Dq 1024
#define Eq 2048
#define Fq 4096
#define Mq (Bq*Nq)   // 4096 tokens

// ---------------- device scratch (no cudaMalloc allowed) ----------------
__device__ __align__(1024) __half g_xn   [(size_t)Mq*Dq];
__device__ __align__(1024) __half g_Q    [(size_t)Mq*Eq];
__device__ __align__(1024) __half g_K    [(size_t)Mq*Eq];
__device__ __align__(1024) __half g_Vt   [(size_t)Mq*Eq];
__device__ __align__(1024) __half g_P    [(size_t)Bq*Nq*Nq];
__device__ __align__(1024) float  g_den  [Mq];
__device__ __align__(1024) float  g_s1   [Mq];
__device__ __align__(1024) float  g_s2   [Mq];
__device__ __align__(1024) __half g_attn [(size_t)Mq*Eq];
__device__ __align__(1024) float  g_x1   [(size_t)Mq*Dq];
__device__ __align__(1024) __half g_xn2  [(size_t)Mq*Dq];
__device__ __align__(1024) __half g_h    [(size_t)Mq*Fq];
__device__ __align__(1024) __half g_qkvT [(size_t)3*Eq*Dq];
__device__ __align__(1024) __half g_oT   [(size_t)Dq*Eq];
__device__ __align__(1024) __half g_w1T  [(size_t)Dq*Fq];
__device__ __align__(1024) __half g_w2T  [(size_t)Dq*Fq];
__device__ int g_cnt[200];
// counter bases
#define CQKV 0
#define CS   32
#define CPV  64
#define CO   96
#define CL   128
#define CF   160
#define CTO  192
#define CW1  193
#define CW2  194

// ---------------- helpers ----------------
__device__ __forceinline__ uint32_t smem_u32(const void* p) {
    uint32_t a;
    asm("{ .reg .u64 t; cvta.to.shared.u64 t, %1; cvt.u32.u64 %0, t; }" : "=r"(a) : "l"(p));
    return a;
}
__device__ __forceinline__ void cp16(uint32_t dst, const void* src) {
    asm volatile("cp.async.cg.shared.global [%0], [%1], 16;" :: "r"(dst), "l"(src) : "memory");
}
#define CP_COMMIT() asm volatile("cp.async.commit_group;" ::: "memory")
#define CP_WAIT1()  asm volatile("cp.async.wait_group 1;" ::: "memory")

__device__ __forceinline__ void ldsm4(uint32_t (&r)[4], uint32_t addr) {
    asm volatile("ldmatrix.sync.aligned.m8n8.x4.shared.b16 {%0,%1,%2,%3}, [%4];"
                 : "=r"(r[0]), "=r"(r[1]), "=r"(r[2]), "=r"(r[3]) : "r"(addr));
}
__device__ __forceinline__ void mma_f16(float (&c)[4], const uint32_t (&a)[4],
                                        uint32_t b0, uint32_t b1) {
    asm volatile("mma.sync.aligned.m16n8k16.row.col.f32.f16.f16.f32 "
                 "{%0,%1,%2,%3}, {%4,%5,%6,%7}, {%8,%9}, {%0,%1,%2,%3};"
                 : "+f"(c[0]), "+f"(c[1]), "+f"(c[2]), "+f"(c[3])
                 : "r"(a[0]), "r"(a[1]), "r"(a[2]), "r"(a[3]), "r"(b0), "r"(b1));
}
__device__ __forceinline__ void st2(float* p, float a, float b) {
    *reinterpret_cast<float2*>(p) = make_float2(a, b);
}
__device__ __forceinline__ void st2(__half* p, float a, float b) {
    *reinterpret_cast<__half2*>(p) = __floats2half2_rn(a, b);
}
__device__ __forceinline__ float gelu_exact(float v) {
    return 0.5f * v * (1.0f + erff(v * 0.70710678118654752f));
}

// spin-wait on counter (consumer) / signal (producer)
__device__ __forceinline__ void waitcnt(int idx, int target) {
    if (threadIdx.x == 0) {
        volatile int* p = &g_cnt[idx];
        while (*p < target) __nanosleep(100);
        __threadfence();
    }
    __syncthreads();
}
__device__ __forceinline__ void postcnt(int idx) {
    __syncthreads();
    if (threadIdx.x == 0) {
        __threadfence();
        atomicAdd(&g_cnt[idx], 1);
    }
}

// 32x32 fp32->fp16 transpose tile (tid = 0..255 flat)
__device__ __forceinline__ void tr_tile(const float* __restrict__ src, __half* __restrict__ dst,
                                        int R, int C, int bid)
{
    __shared__ float t[32][33];
    int txd = threadIdx.x & 31, tyd = threadIdx.x >> 5;
    int tpr = C >> 5;
    int tx = bid % tpr, ty = bid / tpr;
    int c = tx * 32 + txd;
    int r = ty * 32 + tyd;
    #pragma unroll
    for (int dy = 0; dy < 32; dy += 8)
        t[tyd + dy][txd] = src[(size_t)(r + dy) * C + c];
    __syncthreads();
    int c2 = ty * 32 + txd;
    int r2 = tx * 32 + tyd;
    #pragma unroll
    for (int dy = 0; dy < 32; dy += 8)
        dst[(size_t)(r2 + dy) * R + c2] = (__half)t[txd][tyd + dy];
}

// ---------------- GEMM mainloop (device fn): 128x128 CTA, 8 warps 64x32, 3-stage ----------------
__device__ __forceinline__ void gemm_main(const __half* __restrict__ Ab,
                                          const __half* __restrict__ Bb,
                                          int ldA, int ldB, int r0, int c0, int nc,
                                          char* dsm, float (&c)[4][4][4])
{
    uint32_t s0 = (smem_u32(dsm) + 1023u) & ~1023u;
    int tid = threadIdx.x;

    int lm = tid >> 1;
    int cbase = (tid & 1) * 4;
    const __half* gA = Ab + (size_t)(r0 + lm) * ldA + cbase * 8;
    const __half* gB = Bb + (size_t)(c0 + lm) * ldB + cbase * 8;
    uint32_t sw[4];
    #pragma unroll
    for (int i = 0; i < 4; i++)
        sw[i] = (uint32_t)lm * 128u + (uint32_t)(((cbase + i) ^ (lm & 7)) << 4);

    #pragma unroll
    for (int j = 0; j < 2; j++) {
        uint32_t aB = s0 + j * 32768, bB = aB + 16384;
        #pragma unroll
        for (int i = 0; i < 4; i++) {
            cp16(aB + sw[i], gA + j * 64 + i * 8);
            cp16(bB + sw[i], gB + j * 64 + i * 8);
        }
        CP_COMMIT();
    }

    int lane = tid & 31;
    int wm = (tid >> 5) & 1;
    int wn = tid >> 6;
    int aRow = wm * 64 + (lane & 15);
    int aHalf = lane >> 4;
    int bg = lane >> 3;
    int bRow = wn * 32 + ((bg >> 1) * 8) + (lane & 7);
    int bHalf = bg & 1;
    uint32_t aOff = (uint32_t)aRow * 128u;
    uint32_t bOff = (uint32_t)bRow * 128u;
    int aR7 = aRow & 7, bR7 = bRow & 7;

    #pragma unroll
    for (int mt = 0; mt < 4; mt++)
        #pragma unroll
        for (int nt = 0; nt < 4; nt++)
            #pragma unroll
            for (int k = 0; k < 4; k++) c[mt][nt][k] = 0.f;

    int s = 0;
    for (int i = 0; i < nc; i++) {
        CP_WAIT1();
        __syncthreads();
        {
            int j = i + 2;
            if (j < nc) {
                int st = s + 2; if (st >= 3) st -= 3;
                uint32_t aB2 = s0 + st * 32768, bB2 = aB2 + 16384;
                #pragma unroll
                for (int ii = 0; ii < 4; ii++) {
                    cp16(aB2 + sw[ii], gA + (size_t)j * 64 + ii * 8);
                    cp16(bB2 + sw[ii], gB + (size_t)j * 64 + ii * 8);
                }
            }
            CP_COMMIT();
        }
        uint32_t aB = s0 + s * 32768, bB = aB + 16384;
        #pragma unroll
        for (int ks = 0; ks < 4; ks++) {
            uint32_t a[4][4];
            #pragma unroll
            for (int mt = 0; mt < 4; mt++) {
                uint32_t ad = aB + aOff + (uint32_t)(mt * 16 * 128)
                            + (uint32_t)(((ks * 2 + aHalf) ^ aR7) << 4);
                ldsm4(a[mt], ad);
            }
            uint32_t b[8];
            #pragma unroll
            for (int np = 0; np < 2; np++) {
                uint32_t bd = bB + bOff + (uint32_t)(np * 16 * 128)
                            + (uint32_t)(((ks * 2 + bHalf) ^ bR7) << 4);
                uint32_t r[4];
                ldsm4(r, bd);
                b[np*4+0]=r[0]; b[np*4+1]=r[1]; b[np*4+2]=r[2]; b[np*4+3]=r[3];
            }
            #pragma unroll
            for (int mt = 0; mt < 4; mt++) {
                mma_f16(c[mt][0], a[mt], b[0], b[1]);
                mma_f16(c[mt][1], a[mt], b[2], b[3]);
                mma_f16(c[mt][2], a[mt], b[4], b[5]);
                mma_f16(c[mt][3], a[mt], b[6], b[7]);
            }
        }
        if (++s >= 3) s = 0;
    }
}

#define MM_SMEM (3 * 32768 + 1024)
#define TSP 132

// ---------------- prep: qkvT transposes + init + LN1 (critical path only) ----------------
__global__ __launch_bounds__(256)
void prep_kernel(const float* __restrict__ x, const float* __restrict__ ln1_g,
                 const float* __restrict__ ln1_b,
                 const float* __restrict__ q_w, const float* __restrict__ k_w,
                 const float* __restrict__ v_w)
{
    int bid = blockIdx.x;
    if (bid < 6144) {
        int seg = bid >> 11; bid -= seg << 11;
        const float* src = (seg == 0) ? q_w : (seg == 1) ? k_w : v_w;
        tr_tile(src, g_qkvT + (size_t)seg * Eq * Dq, Dq, Eq, bid);
    } else if (bid < 6160) {
        int li = threadIdx.x;
        int idx = (bid - 6144) * 256 + li;
        g_den[idx] = 1e-6f; g_s1[idx] = 0.f; g_s2[idx] = 0.f;
        if (bid == 6144 && li < 200) g_cnt[li] = 0;
    } else {
        int row = bid - 6160;
        int t = threadIdx.x;
        const float4* xr = reinterpret_cast<const float4*>(x + (size_t)row * Dq);
        float4 v = xr[t];
        float s  = v.x + v.y + v.z + v.w;
        float s2r = v.x*v.x + v.y*v.y + v.z*v.z + v.w*v.w;
        __shared__ float rs[8], rs2[8];
        #pragma unroll
        for (int o = 16; o > 0; o >>= 1) {
            s   += __shfl_down_sync(0xffffffffu, s,   o);
            s2r += __shfl_down_sync(0xffffffffu, s2r, o);
        }
        if ((t & 31) == 0) { rs[t >> 5] = s; rs2[t >> 5] = s2r; }
        __syncthreads();
        float ssum = 0.f, ssum2 = 0.f;
        #pragma unroll
        for (int i = 0; i < 8; i++) { ssum += rs[i]; ssum2 += rs2[i]; }
        float mu   = ssum * (1.0f / Dq);
        float var  = ssum2 * (1.0f / Dq) - mu * mu;
        float rstd = rsqrtf(var + 1e-5f);
        float4 gg = reinterpret_cast<const float4*>(ln1_g)[t];
        float4 bb = reinterpret_cast<const float4*>(ln1_b)[t];
        __half2 h01 = __floats2half2_rn((v.x - mu) * rstd * gg.x + bb.x,
                                        (v.y - mu) * rstd * gg.y + bb.y);
        __half2 h23 = __floats2half2_rn((v.z - mu) * rstd * gg.z + bb.z,
                                        (v.w - mu) * rstd * gg.w + bb.w);
        __half2* yp = reinterpret_cast<__half2*>(g_xn + (size_t)row * Dq);
        yp[t * 2]     = h01;
        yp[t * 2 + 1] = h23;
    }
}

// ---------------- mega kernel: everything else, block-level dataflow ----------------
// bid layout:
//     0..1535  QKV              1536..2047  scores         2048..2559  PV
//  2560..4607  oT transpose     4608..8703  w1T transpose  8704..12799 w2T transpose
// 12800..13055 Oproj           13056..13087 LN2           13088..14111 FFN1
// 14112..14367 FFN2
__global__ __launch_bounds__(256, 2)
void mega_kernel(const float* __restrict__ x,
                 const float* __restrict__ q_b, const float* __restrict__ k_b,
                 const float* __restrict__ v_b, const float* __restrict__ o_b,
                 const float* __restrict__ ln2_g, const float* __restrict__ ln2_b,
                 const float* __restrict__ b1, const float* __restrict__ b2,
                 const float* __restrict__ o_w, const float* __restrict__ w1,
                 const float* __restrict__ w2,
                 float* __restrict__ out)
{
    extern __shared__ char dsm[];
    int bid = blockIdx.x;
    int tid = threadIdx.x;
    int lane = tid & 31, wm = (tid >> 5) & 1, wn = tid >> 6;
    int g4 = lane >> 2, q4 = lane & 3;

    if (bid < 1536) {
        // ---- QKV ----
        int rb = bid / 48, ctg = bid % 48;
        int r0 = rb * 128, c0 = ctg * 128;
        float acc[4][4][4];
        gemm_main(g_xn, g_qkvT, Dq, Dq, r0, c0, Dq >> 6, dsm, acc);

        int seg = c0 >> 11;
        const float* biasSel = (seg == 0) ? q_b : (seg == 1) ? k_b : v_b;
        __half* outSel = (seg == 0) ? g_Q : g_K;
        int cSub = c0 - (seg << 11);
        bool vpath = (seg == 2);
        __half* ts = reinterpret_cast<__half*>(dsm);
        if (vpath) __syncthreads();

        #pragma unroll
        for (int mt = 0; mt < 4; mt++) {
            int rl0 = wm * 64 + mt * 16 + g4;
            int row0 = r0 + rl0, row1 = row0 + 8;
            #pragma unroll
            for (int nt = 0; nt < 4; nt++) {
                int lc = wn * 32 + nt * 8 + q4 * 2;
                int colL = cSub + lc;
                float2 bv = *reinterpret_cast<const float2*>(biasSel + colL);
                float v0 = acc[mt][nt][0] + bv.x, v1 = acc[mt][nt][1] + bv.y;
                float v2 = acc[mt][nt][2] + bv.x, v3 = acc[mt][nt][3] + bv.y;
                if (seg < 2) {
                    v0 = (v0 > 0.f) ? (v0 + 1.f) : expf(v0);
                    v1 = (v1 > 0.f) ? (v1 + 1.f) : expf(v1);
                    v2 = (v2 > 0.f) ? (v2 + 1.f) : expf(v2);
                    v3 = (v3 > 0.f) ? (v3 + 1.f) : expf(v3);
                }
                if (vpath) {
                    *reinterpret_cast<__half2*>(ts + rl0 * TSP + lc)       = __floats2half2_rn(v0, v1);
                    *reinterpret_cast<__half2*>(ts + (rl0 + 8) * TSP + lc) = __floats2half2_rn(v2, v3);
                } else {
                    st2(outSel + (size_t)row0 * Eq + colL, v0, v1);
                    st2(outSel + (size_t)row1 * Eq + colL, v2, v3);
                }
            }
        }
        if (vpath) {
            __syncthreads();
            int cc = tid & 127, hh = tid >> 7;
            size_t b = (size_t)(r0 >> 11);
            int seqBase = r0 & 2047;
            __half* dst = g_Vt + b * (size_t)(Nq * Eq) + (size_t)(cSub + cc) * Nq + seqBase + hh * 64;
            #pragma unroll
            for (int i0 = 0; i0 < 64; i0 += 8) {
                __half tmp[8];
                #pragma unroll
                for (int k = 0; k < 8; k++)
                    tmp[k] = ts[(hh * 64 + i0 + k) * TSP + cc];
                *reinterpret_cast<uint4*>(dst + i0) = *reinterpret_cast<const uint4*>(tmp);
            }
        }
        postcnt(CQKV + rb);

    } else if (bid < 2048) {
        // ---- scores ----
        int i = bid - 1536;
        int rtg = i >> 4;
        int bz = rtg >> 4, rt = rtg & 15, ct = i & 15;
        if (ct > rt) return;
        waitcnt(CQKV + rtg, 48);
        waitcnt(CQKV + bz * 16 + ct, 48);
        int r0 = rt * 128, c0 = ct * 128;
        const __half* Ab = g_Q + (size_t)bz * Nq * Eq;
        const __half* Bb = g_K + (size_t)bz * Nq * Eq;
        float acc[4][4][4];
        gemm_main(Ab, Bb, Eq, Eq, r0, c0, Eq >> 6, dsm, acc);

        __half* Cb = g_P + (size_t)bz * Nq * Nq;
        float* denb = g_den + (size_t)bz * Nq;
        #pragma unroll
        for (int mt = 0; mt < 4; mt++) {
            int row0 = r0 + wm * 64 + mt * 16 + g4, row1 = row0 + 8;
            float rs0 = 0.f, rs1 = 0.f;
            #pragma unroll
            for (int nt = 0; nt < 4; nt++) {
                int col = c0 + wn * 32 + nt * 8 + q4 * 2;
                float v0 = acc[mt][nt][0], v1 = acc[mt][nt][1];
                float v2 = acc[mt][nt][2], v3 = acc[mt][nt][3];
                if (col     > row0) v0 = 0.f;
                if (col + 1 > row0) v1 = 0.f;
                if (col     > row1) v2 = 0.f;
                if (col + 1 > row1) v3 = 0.f;
                rs0 += v0 + v1; rs1 += v2 + v3;
                st2(Cb + (size_t)row0 * Nq + col, v0, v1);
                st2(Cb + (size_t)row1 * Nq + col, v2, v3);
            }
            atomicAdd(&denb[row0], rs0);
            atomicAdd(&denb[row1], rs1);
        }
        postcnt(CS + rtg);

    } else if (bid < 2560) {
        // ---- PV ----
        int i = bid - 2048;
        int rtg = i >> 4;
        int bz = rtg >> 4, rt = rtg & 15, ctE = i & 15;
        waitcnt(CS + rtg, rt + 1);
        int r0 = rt * 128, c0 = ctE * 128;
        int nc = (r0 + 128) >> 6;
        const __half* Ab = g_P + (size_t)bz * Nq * Nq;
        const __half* Bb = g_Vt + (size_t)bz * Nq * Eq;
        float acc[4][4][4];
        gemm_main(Ab, Bb, Nq, Nq, r0, c0, nc, dsm, acc);

        __half* Cb = g_attn + (size_t)bz * Nq * Eq;
        const float* denb = g_den + (size_t)bz * Nq;
        #pragma unroll
        for (int mt = 0; mt < 4; mt++) {
            int row0 = r0 + wm * 64 + mt * 16 + g4, row1 = row0 + 8;
            float d0 = 1.0f / denb[row0], d1 = 1.0f / denb[row1];
            #pragma unroll
            for (int nt = 0; nt < 4; nt++) {
                int col = c0 + wn * 32 + nt * 8 + q4 * 2;
                st2(Cb + (size_t)row0 * Eq + col, acc[mt][nt][0] * d0, acc[mt][nt][1] * d0);
                st2(Cb + (size_t)row1 * Eq + col, acc[mt][nt][2] * d1, acc[mt][nt][3] * d1);
            }
        }
        postcnt(CPV + rtg);

    } else if (bid < 4608) {
        // ---- oT transpose ----
        tr_tile(o_w, g_oT, Eq, Dq, bid - 2560);
        postcnt(CTO);
    } else if (bid < 8704) {
        // ---- w1T transpose ----
        tr_tile(w1, g_w1T, Dq, Fq, bid - 4608);
        postcnt(CW1);
    } else if (bid < 12800) {
        // ---- w2T transpose ----
        tr_tile(w2, g_w2T, Fq, Dq, bid - 8704);
        postcnt(CW2);

    } else if (bid < 13056) {
        // ---- Oproj ----
        int i = bid - 12800;
        int mrb = i >> 3, ct = i & 7;
        waitcnt(CTO, 2048);
        waitcnt(CPV + mrb, 16);
        int r0 = mrb * 128, c0 = ct * 128;
        float acc[4][4][4];
        gemm_main(g_attn, g_oT, Eq, Eq, r0, c0, Eq >> 6, dsm, acc);

        #pragma unroll
        for (int mt = 0; mt < 4; mt++) {
            int row0 = r0 + wm * 64 + mt * 16 + g4, row1 = row0 + 8;
            float rs0 = 0.f, rs1 = 0.f, rq0 = 0.f, rq1 = 0.f;
            #pragma unroll
            for (int nt = 0; nt < 4; nt++) {
                int col = c0 + wn * 32 + nt * 8 + q4 * 2;
                float2 bv = *reinterpret_cast<const float2*>(o_b + col);
                float2 r0v = *reinterpret_cast<const float2*>(x + (size_t)row0 * Dq + col);
                float2 r1v = *reinterpret_cast<const float2*>(x + (size_t)row1 * Dq + col);
                float v0 = acc[mt][nt][0] + bv.x + r0v.x;
                float v1 = acc[mt][nt][1] + bv.y + r0v.y;
                float v2 = acc[mt][nt][2] + bv.x + r1v.x;
                float v3 = acc[mt][nt][3] + bv.y + r1v.y;
                rs0 += v0 + v1;        rs1 += v2 + v3;
                rq0 += v0*v0 + v1*v1;  rq1 += v2*v2 + v3*v3;
                st2(g_x1 + (size_t)row0 * Dq + col, v0, v1);
                st2(g_x1 + (size_t)row1 * Dq + col, v2, v3);
            }
            #pragma unroll
            for (int o = 1; o < 4; o <<= 1) {
                rs0 += __shfl_xor_sync(0xffffffffu, rs0, o);
                rs1 += __shfl_xor_sync(0xffffffffu, rs1, o);
                rq0 += __shfl_xor_sync(0xffffffffu, rq0, o);
                rq1 += __shfl_xor_sync(0xffffffffu, rq1, o);
            }
            if (q4 == 0) {
                atomicAdd(&g_s1[row0], rs0);
                atomicAdd(&g_s1[row1], rs1);
                atomicAdd(&g_s2[row0], rq0);
                atomicAdd(&g_s2[row1], rq1);
            }
        }
        postcnt(CO + mrb);

    } else if (bid < 13088) {
        // ---- LN2 (stats precomputed) ----
        int rb = bid - 13056;
        waitcnt(CO + rb, 8);
        int t2 = tid >> 1, half = tid & 1;
        int row = rb * 128 + t2;
        float mu   = g_s1[row] * (1.0f / Dq);
        float var  = g_s2[row] * (1.0f / Dq) - mu * mu;
        float rstd = rsqrtf(var + 1e-5f);
        const float4* xp = reinterpret_cast<const float4*>(g_x1 + (size_t)row * Dq + half * 512);
        const float4* gp = reinterpret_cast<const float4*>(ln2_g) + half * 128;
        const float4* bp = reinterpret_cast<const float4*>(ln2_b) + half * 128;
        __half2* yp = reinterpret_cast<__half2*>(g_xn2 + (size_t)row * Dq + half * 512);
        for (int j = 0; j < 128; j++) {
            float4 v = xp[j];
            float4 gg = gp[j];
            float4 bb = bp[j];
            yp[j * 2]     = __floats2half2_rn((v.x - mu) * rstd * gg.x + bb.x,
                                              (v.y - mu) * rstd * gg.y + bb.y);
            yp[j * 2 + 1] = __floats2half2_rn((v.z - mu) * rstd * gg.z + bb.z,
                                              (v.w - mu) * rstd * gg.w + bb.w);
        }
        postcnt(CL + rb);

    } else if (bid < 14112) {
        // ---- FFN1 ----
        int i = bid - 13088;
        int mrb = i >> 5, ct = i & 31;
        waitcnt(CW1, 4096);
        waitcnt(CL + mrb, 1);
        int r0 = mrb * 128, c0 = ct * 128;
        float acc[4][4][4];
        gemm_main(g_xn2, g_w1T, Dq, Dq, r0, c0, Dq >> 6, dsm, acc);

        #pragma unroll
        for (int mt = 0; mt < 4; mt++) {
            int row0 = r0 + wm * 64 + mt * 16 + g4, row1 = row0 + 8;
            #pragma unroll
            for (int nt = 0; nt < 4; nt++) {
                int col = c0 + wn * 32 + nt * 8 + q4 * 2;
                float2 bv = *reinterpret_cast<const float2*>(b1 + col);
                float v0 = gelu_exact(acc[mt][nt][0] + bv.x);
                float v1 = gelu_exact(acc[mt][nt][1] + bv.y);
                float v2 = gelu_exact(acc[mt][nt][2] + bv.x);
                float v3 = gelu_exact(acc[mt][nt][3] + bv.y);
                st2(g_h + (size_t)row0 * Fq + col, v0, v1);
                st2(g_h + (size_t)row1 * Fq + col, v2, v3);
            }
        }
        postcnt(CF + mrb);

    } else {
        // ---- FFN2 ----
        int i = bid - 14112;
        int mrb = i >> 3, ct = i & 7;
        waitcnt(CW2, 4096);
        waitcnt(CF + mrb, 32);
        int r0 = mrb * 128, c0 = ct * 128;
        float acc[4][4][4];
        gemm_main(g_h, g_w2T, Fq, Fq, r0, c0, Fq >> 6, dsm, acc);

        #pragma unroll
        for (int mt = 0; mt < 4; mt++) {
            int row0 = r0 + wm * 64 + mt * 16 + g4, row1 = row0 + 8;
            #pragma unroll
            for (int nt = 0; nt < 4; nt++) {
                int col = c0 + wn * 32 + nt * 8 + q4 * 2;
                float2 bv = *reinterpret_cast<const float2*>(b2 + col);
                float2 r0v = *reinterpret_cast<const float2*>(g_x1 + (size_t)row0 * Dq + col);
                float2 r1v = *reinterpret_cast<const float2*>(g_x1 + (size_t)row1 * Dq + col);
                st2(out + (size_t)row0 * Dq + col, acc[mt][nt][0] + bv.x + r0v.x,
                                                   acc[mt][nt][1] + bv.y + r0v.y);
                st2(out + (size_t)row1 * Dq + col, acc[mt][nt][2] + bv.x + r1v.x,
                                                   acc[mt][nt][3] + bv.y + r1v.y);
            }
        }
    }
}

// ---------------- launch ----------------
extern "C" void kernel_launch(void* const* d_in, const int* in_sizes, int n_in,
                              void* d_out, int out_size)
{
    const float* x     = (const float*)d_in[0];
    const float* q_w   = (const float*)d_in[1];
    const float* q_b   = (const float*)d_in[2];
    const float* k_w   = (const float*)d_in[3];
    const float* k_b   = (const float*)d_in[4];
    const float* v_w   = (const float*)d_in[5];
    const float* v_b   = (const float*)d_in[6];
    const float* o_w   = (const float*)d_in[7];
    const float* o_b   = (const float*)d_in[8];
    const float* ln1_g = (const float*)d_in[9];
    const float* ln1_b = (const float*)d_in[10];
    const float* ln2_g = (const float*)d_in[11];
    const float* ln2_b = (const float*)d_in[12];
    const float* w1    = (const float*)d_in[13];
    const float* b1    = (const float*)d_in[14];
    const float* w2    = (const float*)d_in[15];
    const float* b2    = (const float*)d_in[16];
    float* out = (float*)d_out;

    cudaFuncSetAttribute(mega_kernel, cudaFuncAttributeMaxDynamicSharedMemorySize, MM_SMEM);

    // prep: qkvT transposes + init + LN1 (critical path only)
    prep_kernel<<<10256, 256>>>(x, ln1_g, ln1_b, q_w, k_w, v_w);

    // everything else in one launch; oT/w1T/w2T transposes overlap with attention
    mega_kernel<<<14368, 256, MM_SMEM>>>(x, q_b, k_b, v_b, o_b, ln2_g, ln2_b,
                                         b1, b2, o_w, w1, w2, out);
}

// round 13
// speedup vs baseline: 1.1177x; 1.1177x over previous
#include <cuda_runtime.h>
#include <cuda_fp16.h>
#include <math.h>
#include <stdint.h>

// Problem shapes (fixed)
#define Bq 2
#define Nq 2048
#define Dq 1024
#define Eq 2048
#define Fq 4096
#define Mq (Bq*Nq)   // 4096 tokens

// ---------------- device scratch (no cudaMalloc allowed) ----------------
__device__ __align__(1024) __half g_xn   [(size_t)Mq*Dq];
__device__ __align__(1024) __half g_Q    [(size_t)Mq*Eq];
__device__ __align__(1024) __half g_K    [(size_t)Mq*Eq];
__device__ __align__(1024) __half g_Vt   [(size_t)Mq*Eq];
__device__ __align__(1024) __half g_P    [(size_t)Bq*Nq*Nq];
__device__ __align__(1024) float  g_den  [Mq];
__device__ __align__(1024) float  g_s1   [Mq];
__device__ __align__(1024) float  g_s2   [Mq];
__device__ __align__(1024) __half g_attn [(size_t)Mq*Eq];
__device__ __align__(1024) float  g_x1   [(size_t)Mq*Dq];
__device__ __align__(1024) __half g_xn2  [(size_t)Mq*Dq];
__device__ __align__(1024) __half g_h    [(size_t)Mq*Fq];
__device__ __align__(1024) __half g_qkvT [(size_t)3*Eq*Dq];
__device__ __align__(1024) __half g_oT   [(size_t)Dq*Eq];
__device__ __align__(1024) __half g_w1T  [(size_t)Dq*Fq];
__device__ __align__(1024) __half g_w2T  [(size_t)Dq*Fq];
__device__ int g_cnt[192];
// counter bases
#define CQKV 0
#define CS   32
#define CPV  64
#define CO   96
#define CL   128
#define CF   160

// ---------------- helpers ----------------
__device__ __forceinline__ uint32_t smem_u32(const void* p) {
    uint32_t a;
    asm("{ .reg .u64 t; cvta.to.shared.u64 t, %1; cvt.u32.u64 %0, t; }" : "=r"(a) : "l"(p));
    return a;
}
__device__ __forceinline__ void cp16(uint32_t dst, const void* src) {
    asm volatile("cp.async.cg.shared.global [%0], [%1], 16;" :: "r"(dst), "l"(src) : "memory");
}
#define CP_COMMIT() asm volatile("cp.async.commit_group;" ::: "memory")
#define CP_WAIT1()  asm volatile("cp.async.wait_group 1;" ::: "memory")

__device__ __forceinline__ void ldsm4(uint32_t (&r)[4], uint32_t addr) {
    asm volatile("ldmatrix.sync.aligned.m8n8.x4.shared.b16 {%0,%1,%2,%3}, [%4];"
                 : "=r"(r[0]), "=r"(r[1]), "=r"(r[2]), "=r"(r[3]) : "r"(addr));
}
__device__ __forceinline__ void mma_f16(float (&c)[4], const uint32_t (&a)[4],
                                        uint32_t b0, uint32_t b1) {
    asm volatile("mma.sync.aligned.m16n8k16.row.col.f32.f16.f16.f32 "
                 "{%0,%1,%2,%3}, {%4,%5,%6,%7}, {%8,%9}, {%0,%1,%2,%3};"
                 : "+f"(c[0]), "+f"(c[1]), "+f"(c[2]), "+f"(c[3])
                 : "r"(a[0]), "r"(a[1]), "r"(a[2]), "r"(a[3]), "r"(b0), "r"(b1));
}
__device__ __forceinline__ void st2(float* p, float a, float b) {
    *reinterpret_cast<float2*>(p) = make_float2(a, b);
}
__device__ __forceinline__ void st2(__half* p, float a, float b) {
    *reinterpret_cast<__half2*>(p) = __floats2half2_rn(a, b);
}
__device__ __forceinline__ float gelu_exact(float v) {
    return 0.5f * v * (1.0f + erff(v * 0.70710678118654752f));
}

// spin-wait on counter (consumer) / signal (producer)
__device__ __forceinline__ void waitcnt(int idx, int target) {
    if (threadIdx.x == 0) {
        volatile int* p = &g_cnt[idx];
        while (*p < target) __nanosleep(100);
        __threadfence();
    }
    __syncthreads();
}
__device__ __forceinline__ void postcnt(int idx) {
    __syncthreads();
    if (threadIdx.x == 0) {
        __threadfence();
        atomicAdd(&g_cnt[idx], 1);
    }
}

// 64x32 fp32->fp16 transpose tile; warp-wide 128B half2 output rows
__device__ __forceinline__ void tr_tile64(const float* __restrict__ src, __half* __restrict__ dst,
                                          int R, int C, int bid)
{
    __shared__ float t[64][33];
    int tid = threadIdx.x;
    int tpr = C >> 5;
    int tx = bid % tpr, ty = bid / tpr;     // ty: 64-row tile (R), tx: 32-col tile (C)
    int c = tx * 32 + (tid & 31);
    int rb = ty * 64;
    int r0 = tid >> 5;                      // 0..7
    #pragma unroll
    for (int dy = 0; dy < 64; dy += 8)
        t[r0 + dy][tid & 31] = src[(size_t)(rb + r0 + dy) * C + c];
    __syncthreads();
    int lane = tid & 31, w = tid >> 5;
    #pragma unroll
    for (int i = 0; i < 4; i++) {
        int co = w + i * 8;                 // 0..31
        __half2 v = __floats2half2_rn(t[2 * lane][co], t[2 * lane + 1][co]);
        *reinterpret_cast<__half2*>(dst + (size_t)(tx * 32 + co) * R + rb + 2 * lane) = v;
    }
}

// ---------------- GEMM mainloop (device fn): 128x128 CTA, 8 warps 64x32, 3-stage ----------------
__device__ __forceinline__ void gemm_main(const __half* __restrict__ Ab,
                                          const __half* __restrict__ Bb,
                                          int ldA, int ldB, int r0, int c0, int nc,
                                          char* dsm, float (&c)[4][4][4])
{
    uint32_t s0 = (smem_u32(dsm) + 1023u) & ~1023u;
    int tid = threadIdx.x;

    int lm = tid >> 1;
    int cbase = (tid & 1) * 4;
    const __half* gA = Ab + (size_t)(r0 + lm) * ldA + cbase * 8;
    const __half* gB = Bb + (size_t)(c0 + lm) * ldB + cbase * 8;
    uint32_t sw[4];
    #pragma unroll
    for (int i = 0; i < 4; i++)
        sw[i] = (uint32_t)lm * 128u + (uint32_t)(((cbase + i) ^ (lm & 7)) << 4);

    #pragma unroll
    for (int j = 0; j < 2; j++) {
        uint32_t aB = s0 + j * 32768, bB = aB + 16384;
        #pragma unroll
        for (int i = 0; i < 4; i++) {
            cp16(aB + sw[i], gA + j * 64 + i * 8);
            cp16(bB + sw[i], gB + j * 64 + i * 8);
        }
        CP_COMMIT();
    }

    int lane = tid & 31;
    int wm = (tid >> 5) & 1;
    int wn = tid >> 6;
    int aRow = wm * 64 + (lane & 15);
    int aHalf = lane >> 4;
    int bg = lane >> 3;
    int bRow = wn * 32 + ((bg >> 1) * 8) + (lane & 7);
    int bHalf = bg & 1;
    uint32_t aOff = (uint32_t)aRow * 128u;
    uint32_t bOff = (uint32_t)bRow * 128u;
    int aR7 = aRow & 7, bR7 = bRow & 7;

    #pragma unroll
    for (int mt = 0; mt < 4; mt++)
        #pragma unroll
        for (int nt = 0; nt < 4; nt++)
            #pragma unroll
            for (int k = 0; k < 4; k++) c[mt][nt][k] = 0.f;

    int s = 0;
    for (int i = 0; i < nc; i++) {
        CP_WAIT1();
        __syncthreads();
        {
            int j = i + 2;
            if (j < nc) {
                int st = s + 2; if (st >= 3) st -= 3;
                uint32_t aB2 = s0 + st * 32768, bB2 = aB2 + 16384;
                #pragma unroll
                for (int ii = 0; ii < 4; ii++) {
                    cp16(aB2 + sw[ii], gA + (size_t)j * 64 + ii * 8);
                    cp16(bB2 + sw[ii], gB + (size_t)j * 64 + ii * 8);
                }
            }
            CP_COMMIT();
        }
        uint32_t aB = s0 + s * 32768, bB = aB + 16384;
        #pragma unroll
        for (int ks = 0; ks < 4; ks++) {
            uint32_t a[4][4];
            #pragma unroll
            for (int mt = 0; mt < 4; mt++) {
                uint32_t ad = aB + aOff + (uint32_t)(mt * 16 * 128)
                            + (uint32_t)(((ks * 2 + aHalf) ^ aR7) << 4);
                ldsm4(a[mt], ad);
            }
            uint32_t b[8];
            #pragma unroll
            for (int np = 0; np < 2; np++) {
                uint32_t bd = bB + bOff + (uint32_t)(np * 16 * 128)
                            + (uint32_t)(((ks * 2 + bHalf) ^ bR7) << 4);
                uint32_t r[4];
                ldsm4(r, bd);
                b[np*4+0]=r[0]; b[np*4+1]=r[1]; b[np*4+2]=r[2]; b[np*4+3]=r[3];
            }
            #pragma unroll
            for (int mt = 0; mt < 4; mt++) {
                mma_f16(c[mt][0], a[mt], b[0], b[1]);
                mma_f16(c[mt][1], a[mt], b[2], b[3]);
                mma_f16(c[mt][2], a[mt], b[4], b[5]);
                mma_f16(c[mt][3], a[mt], b[6], b[7]);
            }
        }
        if (++s >= 3) s = 0;
    }
}

#define MM_SMEM (3 * 32768 + 1024)
#define TSP 132

// ---------------- prep: all transposes + init + LN1 (thin-smem kernel) ----------------
// bid: [0,3072) qkvT  [3072,4096) oT  [4096,6144) w1T  [6144,8192) w2T
//      [8192,8208) init  [8208,12304) LN1
__global__ __launch_bounds__(256)
void prep_kernel(const float* __restrict__ x, const float* __restrict__ ln1_g,
                 const float* __restrict__ ln1_b,
                 const float* __restrict__ q_w, const float* __restrict__ k_w,
                 const float* __restrict__ v_w, const float* __restrict__ o_w,
                 const float* __restrict__ w1,  const float* __restrict__ w2)
{
    int bid = blockIdx.x;
    if (bid < 3072) {
        int seg = bid >> 10; bid -= seg << 10;   // 1024 tiles per matrix (16x64)
        const float* src = (seg == 0) ? q_w : (seg == 1) ? k_w : v_w;
        tr_tile64(src, g_qkvT + (size_t)seg * Eq * Dq, Dq, Eq, bid);
    } else if (bid < 4096) {
        tr_tile64(o_w, g_oT, Eq, Dq, bid - 3072);       // 32x32 = 1024 tiles
    } else if (bid < 6144) {
        tr_tile64(w1, g_w1T, Dq, Fq, bid - 4096);       // 16x128 = 2048 tiles
    } else if (bid < 8192) {
        tr_tile64(w2, g_w2T, Fq, Dq, bid - 6144);       // 64x32 = 2048 tiles
    } else if (bid < 8208) {
        int li = threadIdx.x;
        int idx = (bid - 8192) * 256 + li;
        g_den[idx] = 1e-6f; g_s1[idx] = 0.f; g_s2[idx] = 0.f;
        if (bid == 8192 && li < 192) g_cnt[li] = 0;
    } else {
        int row = bid - 8208;
        int t = threadIdx.x;
        const float4* xr = reinterpret_cast<const float4*>(x + (size_t)row * Dq);
        float4 v = xr[t];
        float s  = v.x + v.y + v.z + v.w;
        float s2r = v.x*v.x + v.y*v.y + v.z*v.z + v.w*v.w;
        __shared__ float rs[8], rs2[8];
        #pragma unroll
        for (int o = 16; o > 0; o >>= 1) {
            s   += __shfl_down_sync(0xffffffffu, s,   o);
            s2r += __shfl_down_sync(0xffffffffu, s2r, o);
        }
        if ((t & 31) == 0) { rs[t >> 5] = s; rs2[t >> 5] = s2r; }
        __syncthreads();
        float ssum = 0.f, ssum2 = 0.f;
        #pragma unroll
        for (int i = 0; i < 8; i++) { ssum += rs[i]; ssum2 += rs2[i]; }
        float mu   = ssum * (1.0f / Dq);
        float var  = ssum2 * (1.0f / Dq) - mu * mu;
        float rstd = rsqrtf(var + 1e-5f);
        float4 gg = reinterpret_cast<const float4*>(ln1_g)[t];
        float4 bb = reinterpret_cast<const float4*>(ln1_b)[t];
        __half2 h01 = __floats2half2_rn((v.x - mu) * rstd * gg.x + bb.x,
                                        (v.y - mu) * rstd * gg.y + bb.y);
        __half2 h23 = __floats2half2_rn((v.z - mu) * rstd * gg.z + bb.z,
                                        (v.w - mu) * rstd * gg.w + bb.w);
        __half2* yp = reinterpret_cast<__half2*>(g_xn + (size_t)row * Dq);
        yp[t * 2]     = h01;
        yp[t * 2 + 1] = h23;
    }
}

// ---------------- mega kernel: entire layer after prep, block-level dataflow ----------------
__global__ __launch_bounds__(256, 2)
void mega_kernel(const float* __restrict__ x,
                 const float* __restrict__ q_b, const float* __restrict__ k_b,
                 const float* __restrict__ v_b, const float* __restrict__ o_b,
                 const float* __restrict__ ln2_g, const float* __restrict__ ln2_b,
                 const float* __restrict__ b1, const float* __restrict__ b2,
                 float* __restrict__ out)
{
    extern __shared__ char dsm[];
    int bid = blockIdx.x;
    int tid = threadIdx.x;
    int lane = tid & 31, wm = (tid >> 5) & 1, wn = tid >> 6;
    int g4 = lane >> 2, q4 = lane & 3;

    if (bid < 1536) {
        // ---- QKV ----
        int rb = bid / 48, ctg = bid % 48;
        int r0 = rb * 128, c0 = ctg * 128;
        float acc[4][4][4];
        gemm_main(g_xn, g_qkvT, Dq, Dq, r0, c0, Dq >> 6, dsm, acc);

        int seg = c0 >> 11;
        const float* biasSel = (seg == 0) ? q_b : (seg == 1) ? k_b : v_b;
        __half* outSel = (seg == 0) ? g_Q : g_K;
        int cSub = c0 - (seg << 11);
        bool vpath = (seg == 2);
        __half* ts = reinterpret_cast<__half*>(dsm);
        if (vpath) __syncthreads();

        #pragma unroll
        for (int mt = 0; mt < 4; mt++) {
            int rl0 = wm * 64 + mt * 16 + g4;
            int row0 = r0 + rl0, row1 = row0 + 8;
            #pragma unroll
            for (int nt = 0; nt < 4; nt++) {
                int lc = wn * 32 + nt * 8 + q4 * 2;
                int colL = cSub + lc;
                float2 bv = *reinterpret_cast<const float2*>(biasSel + colL);
                float v0 = acc[mt][nt][0] + bv.x, v1 = acc[mt][nt][1] + bv.y;
                float v2 = acc[mt][nt][2] + bv.x, v3 = acc[mt][nt][3] + bv.y;
                if (seg < 2) {
                    v0 = (v0 > 0.f) ? (v0 + 1.f) : expf(v0);
                    v1 = (v1 > 0.f) ? (v1 + 1.f) : expf(v1);
                    v2 = (v2 > 0.f) ? (v2 + 1.f) : expf(v2);
                    v3 = (v3 > 0.f) ? (v3 + 1.f) : expf(v3);
                }
                if (vpath) {
                    *reinterpret_cast<__half2*>(ts + rl0 * TSP + lc)       = __floats2half2_rn(v0, v1);
                    *reinterpret_cast<__half2*>(ts + (rl0 + 8) * TSP + lc) = __floats2half2_rn(v2, v3);
                } else {
                    st2(outSel + (size_t)row0 * Eq + colL, v0, v1);
                    st2(outSel + (size_t)row1 * Eq + colL, v2, v3);
                }
            }
        }
        if (vpath) {
            __syncthreads();
            int cc = tid & 127, hh = tid >> 7;
            size_t b = (size_t)(r0 >> 11);
            int seqBase = r0 & 2047;
            __half* dst = g_Vt + b * (size_t)(Nq * Eq) + (size_t)(cSub + cc) * Nq + seqBase + hh * 64;
            #pragma unroll
            for (int i0 = 0; i0 < 64; i0 += 8) {
                __half tmp[8];
                #pragma unroll
                for (int k = 0; k < 8; k++)
                    tmp[k] = ts[(hh * 64 + i0 + k) * TSP + cc];
                *reinterpret_cast<uint4*>(dst + i0) = *reinterpret_cast<const uint4*>(tmp);
            }
        }
        postcnt(CQKV + rb);

    } else if (bid < 2048) {
        // ---- scores ----
        int i = bid - 1536;
        int rtg = i >> 4;
        int bz = rtg >> 4, rt = rtg & 15, ct = i & 15;
        if (ct > rt) return;
        waitcnt(CQKV + rtg, 48);
        waitcnt(CQKV + bz * 16 + ct, 48);
        int r0 = rt * 128, c0 = ct * 128;
        const __half* Ab = g_Q + (size_t)bz * Nq * Eq;
        const __half* Bb = g_K + (size_t)bz * Nq * Eq;
        float acc[4][4][4];
        gemm_main(Ab, Bb, Eq, Eq, r0, c0, Eq >> 6, dsm, acc);

        __half* Cb = g_P + (size_t)bz * Nq * Nq;
        float* denb = g_den + (size_t)bz * Nq;
        #pragma unroll
        for (int mt = 0; mt < 4; mt++) {
            int row0 = r0 + wm * 64 + mt * 16 + g4, row1 = row0 + 8;
            float rs0 = 0.f, rs1 = 0.f;
            #pragma unroll
            for (int nt = 0; nt < 4; nt++) {
                int col = c0 + wn * 32 + nt * 8 + q4 * 2;
                float v0 = acc[mt][nt][0], v1 = acc[mt][nt][1];
                float v2 = acc[mt][nt][2], v3 = acc[mt][nt][3];
                if (col     > row0) v0 = 0.f;
                if (col + 1 > row0) v1 = 0.f;
                if (col     > row1) v2 = 0.f;
                if (col + 1 > row1) v3 = 0.f;
                rs0 += v0 + v1; rs1 += v2 + v3;
                st2(Cb + (size_t)row0 * Nq + col, v0, v1);
                st2(Cb + (size_t)row1 * Nq + col, v2, v3);
            }
            atomicAdd(&denb[row0], rs0);
            atomicAdd(&denb[row1], rs1);
        }
        postcnt(CS + rtg);

    } else if (bid < 2560) {
        // ---- PV ----
        int i = bid - 2048;
        int rtg = i >> 4;
        int bz = rtg >> 4, rt = rtg & 15, ctE = i & 15;
        waitcnt(CS + rtg, rt + 1);
        int r0 = rt * 128, c0 = ctE * 128;
        int nc = (r0 + 128) >> 6;
        const __half* Ab = g_P + (size_t)bz * Nq * Nq;
        const __half* Bb = g_Vt + (size_t)bz * Nq * Eq;
        float acc[4][4][4];
        gemm_main(Ab, Bb, Nq, Nq, r0, c0, nc, dsm, acc);

        __half* Cb = g_attn + (size_t)bz * Nq * Eq;
        const float* denb = g_den + (size_t)bz * Nq;
        #pragma unroll
        for (int mt = 0; mt < 4; mt++) {
            int row0 = r0 + wm * 64 + mt * 16 + g4, row1 = row0 + 8;
            float d0 = 1.0f / denb[row0], d1 = 1.0f / denb[row1];
            #pragma unroll
            for (int nt = 0; nt < 4; nt++) {
                int col = c0 + wn * 32 + nt * 8 + q4 * 2;
                st2(Cb + (size_t)row0 * Eq + col, acc[mt][nt][0] * d0, acc[mt][nt][1] * d0);
                st2(Cb + (size_t)row1 * Eq + col, acc[mt][nt][2] * d1, acc[mt][nt][3] * d1);
            }
        }
        postcnt(CPV + rtg);

    } else if (bid < 2816) {
        // ---- Oproj ----
        int i = bid - 2560;
        int mrb = i >> 3, ct = i & 7;
        waitcnt(CPV + mrb, 16);
        int r0 = mrb * 128, c0 = ct * 128;
        float acc[4][4][4];
        gemm_main(g_attn, g_oT, Eq, Eq, r0, c0, Eq >> 6, dsm, acc);

        #pragma unroll
        for (int mt = 0; mt < 4; mt++) {
            int row0 = r0 + wm * 64 + mt * 16 + g4, row1 = row0 + 8;
            float rs0 = 0.f, rs1 = 0.f, rq0 = 0.f, rq1 = 0.f;
            #pragma unroll
            for (int nt = 0; nt < 4; nt++) {
                int col = c0 + wn * 32 + nt * 8 + q4 * 2;
                float2 bv = *reinterpret_cast<const float2*>(o_b + col);
                float2 r0v = *reinterpret_cast<const float2*>(x + (size_t)row0 * Dq + col);
                float2 r1v = *reinterpret_cast<const float2*>(x + (size_t)row1 * Dq + col);
                float v0 = acc[mt][nt][0] + bv.x + r0v.x;
                float v1 = acc[mt][nt][1] + bv.y + r0v.y;
                float v2 = acc[mt][nt][2] + bv.x + r1v.x;
                float v3 = acc[mt][nt][3] + bv.y + r1v.y;
                rs0 += v0 + v1;        rs1 += v2 + v3;
                rq0 += v0*v0 + v1*v1;  rq1 += v2*v2 + v3*v3;
                st2(g_x1 + (size_t)row0 * Dq + col, v0, v1);
                st2(g_x1 + (size_t)row1 * Dq + col, v2, v3);
            }
            #pragma unroll
            for (int o = 1; o < 4; o <<= 1) {
                rs0 += __shfl_xor_sync(0xffffffffu, rs0, o);
                rs1 += __shfl_xor_sync(0xffffffffu, rs1, o);
                rq0 += __shfl_xor_sync(0xffffffffu, rq0, o);
                rq1 += __shfl_xor_sync(0xffffffffu, rq1, o);
            }
            if (q4 == 0) {
                atomicAdd(&g_s1[row0], rs0);
                atomicAdd(&g_s1[row1], rs1);
                atomicAdd(&g_s2[row0], rq0);
                atomicAdd(&g_s2[row1], rq1);
            }
        }
        postcnt(CO + mrb);

    } else if (bid < 2848) {
        // ---- LN2 (stats precomputed) ----
        int rb = bid - 2816;
        waitcnt(CO + rb, 8);
        int t2 = tid >> 1, half = tid & 1;
        int row = rb * 128 + t2;
        float mu   = g_s1[row] * (1.0f / Dq);
        float var  = g_s2[row] * (1.0f / Dq) - mu * mu;
        float rstd = rsqrtf(var + 1e-5f);
        const float4* xp = reinterpret_cast<const float4*>(g_x1 + (size_t)row * Dq + half * 512);
        const float4* gp = reinterpret_cast<const float4*>(ln2_g) + half * 128;
        const float4* bp = reinterpret_cast<const float4*>(ln2_b) + half * 128;
        __half2* yp = reinterpret_cast<__half2*>(g_xn2 + (size_t)row * Dq + half * 512);
        for (int j = 0; j < 128; j++) {
            float4 v = xp[j];
            float4 gg = gp[j];
            float4 bb = bp[j];
            yp[j * 2]     = __floats2half2_rn((v.x - mu) * rstd * gg.x + bb.x,
                                              (v.y - mu) * rstd * gg.y + bb.y);
            yp[j * 2 + 1] = __floats2half2_rn((v.z - mu) * rstd * gg.z + bb.z,
                                              (v.w - mu) * rstd * gg.w + bb.w);
        }
        postcnt(CL + rb);

    } else if (bid < 3872) {
        // ---- FFN1 ----
        int i = bid - 2848;
        int mrb = i >> 5, ct = i & 31;
        waitcnt(CL + mrb, 1);
        int r0 = mrb * 128, c0 = ct * 128;
        float acc[4][4][4];
        gemm_main(g_xn2, g_w1T, Dq, Dq, r0, c0, Dq >> 6, dsm, acc);

        #pragma unroll
        for (int mt = 0; mt < 4; mt++) {
            int row0 = r0 + wm * 64 + mt * 16 + g4, row1 = row0 + 8;
            #pragma unroll
            for (int nt = 0; nt < 4; nt++) {
                int col = c0 + wn * 32 + nt * 8 + q4 * 2;
                float2 bv = *reinterpret_cast<const float2*>(b1 + col);
                float v0 = gelu_exact(acc[mt][nt][0] + bv.x);
                float v1 = gelu_exact(acc[mt][nt][1] + bv.y);
                float v2 = gelu_exact(acc[mt][nt][2] + bv.x);
                float v3 = gelu_exact(acc[mt][nt][3] + bv.y);
                st2(g_h + (size_t)row0 * Fq + col, v0, v1);
                st2(g_h + (size_t)row1 * Fq + col, v2, v3);
            }
        }
        postcnt(CF + mrb);

    } else {
        // ---- FFN2 ----
        int i = bid - 3872;
        int mrb = i >> 3, ct = i & 7;
        waitcnt(CF + mrb, 32);
        int r0 = mrb * 128, c0 = ct * 128;
        float acc[4][4][4];
        gemm_main(g_h, g_w2T, Fq, Fq, r0, c0, Fq >> 6, dsm, acc);

        #pragma unroll
        for (int mt = 0; mt < 4; mt++) {
            int row0 = r0 + wm * 64 + mt * 16 + g4, row1 = row0 + 8;
            #pragma unroll
            for (int nt = 0; nt < 4; nt++) {
                int col = c0 + wn * 32 + nt * 8 + q4 * 2;
                float2 bv = *reinterpret_cast<const float2*>(b2 + col);
                float2 r0v = *reinterpret_cast<const float2*>(g_x1 + (size_t)row0 * Dq + col);
                float2 r1v = *reinterpret_cast<const float2*>(g_x1 + (size_t)row1 * Dq + col);
                st2(out + (size_t)row0 * Dq + col, acc[mt][nt][0] + bv.x + r0v.x,
                                                   acc[mt][nt][1] + bv.y + r0v.y);
                st2(out + (size_t)row1 * Dq + col, acc[mt][nt][2] + bv.x + r1v.x,
                                                   acc[mt][nt][3] + bv.y + r1v.y);
            }
        }
    }
}

// ---------------- launch ----------------
extern "C" void kernel_launch(void* const* d_in, const int* in_sizes, int n_in,
                              void* d_out, int out_size)
{
    const float* x     = (const float*)d_in[0];
    const float* q_w   = (const float*)d_in[1];
    const float* q_b   = (const float*)d_in[2];
    const float* k_w   = (const float*)d_in[3];
    const float* k_b   = (const float*)d_in[4];
    const float* v_w   = (const float*)d_in[5];
    const float* v_b   = (const float*)d_in[6];
    const float* o_w   = (const float*)d_in[7];
    const float* o_b   = (const float*)d_in[8];
    const float* ln1_g = (const float*)d_in[9];
    const float* ln1_b = (const float*)d_in[10];
    const float* ln2_g = (const float*)d_in[11];
    const float* ln2_b = (const float*)d_in[12];
    const float* w1    = (const float*)d_in[13];
    const float* b1    = (const float*)d_in[14];
    const float* w2    = (const float*)d_in[15];
    const float* b2    = (const float*)d_in[16];
    float* out = (float*)d_out;

    cudaFuncSetAttribute(mega_kernel, cudaFuncAttributeMaxDynamicSharedMemorySize, MM_SMEM);

    // prep: all weight transposes (half2 stores) + init + LN1
    prep_kernel<<<12304, 256>>>(x, ln1_g, ln1_b, q_w, k_w, v_w, o_w, w1, w2);

    // everything else in one launch with block-level dataflow
    mega_kernel<<<4128, 256, MM_SMEM>>>(x, q_b, k_b, v_b, o_b, ln2_g, ln2_b, b1, b2, out);
}